// round 14
// baseline (speedup 1.0000x reference)
#include <cuda_runtime.h>
#include <cuda_bf16.h>

#define H      128
#define IN_D   8
#define TT     512
#define OUTD   4
#define FCH    64
#define MB     32
#define NTHR   512
#define NCHUNK 25               // chunks per step: 1(Wih0,k8) + 8(Whh0) + 8(Whh1) + 8(Wih1)
#define APW    40               // u32 row stride of activation buffers (32 + 8 pad)
#define CHUNKU 8192             // u32 per chunk (32 KB): 16 warps x 32 lanes x 16
#define NSLOT  4

typedef unsigned u32;

// weights permuted to per-(chunk, warp, lane) fragment order, bf16 hi/lo packed,
// uint4-rotated within each lane block for conflict-free LDS.128 without padding
__device__ __align__(128) u32 g_Wperm[NCHUNK * CHUNKU];   // 800KB
__device__ float g_W1T[H * FCH];
__device__ float g_b0[512], g_b1[512], g_bnsc[H], g_bnsh[H];

__global__ void prep_kernel(const float* __restrict__ Wih0, const float* __restrict__ Whh0,
                            const float* __restrict__ bih0, const float* __restrict__ bhh0,
                            const float* __restrict__ Wih1, const float* __restrict__ Whh1,
                            const float* __restrict__ bih1, const float* __restrict__ bhh1,
                            const float* __restrict__ gam,  const float* __restrict__ bet,
                            const float* __restrict__ mean, const float* __restrict__ var,
                            const float* __restrict__ W1)
{
    int i0 = blockIdx.x * blockDim.x + threadIdx.x;
    int st = gridDim.x * blockDim.x;

    for (int idx = i0; idx < NCHUNK * 16 * 32 * 16; idx += st) {
        int part = idx & 3;          // u32 within logical uint4
        int g    = (idx >> 2) & 3;   // logical uint4 index = gate
        int lane = (idx >> 4) & 31;
        int w    = (idx >> 9) & 15;
        int r    = idx >> 13;
        int laneK = lane & 3, laneM = lane >> 2;
        int n = g * 128 + w * 8 + laneM;            // output column 0..511
        int kk = 2 * laneK + ((part & 1) ? 8 : 0);  // k within chunk
        bool isLo = (part >= 2);
        const float* Wm; int K, kb;
        if (r == 0)       { Wm = Wih0; K = IN_D; kb = 0; }
        else if (r <= 8)  { Wm = Whh0; K = H; kb = (r - 1)  * 16; }
        else if (r <= 16) { Wm = Whh1; K = H; kb = (r - 9)  * 16; }   // h1 half FIRST
        else              { Wm = Wih1; K = H; kb = (r - 17) * 16; }   // h0(new) half second
        u32 val = 0;
        if (kb + kk < K) {
            float w0 = Wm[n * K + kb + kk];
            float w1 = Wm[n * K + kb + kk + 1];
            __nv_bfloat16 hb0 = __float2bfloat16_rn(w0);
            __nv_bfloat16 hb1 = __float2bfloat16_rn(w1);
            __nv_bfloat162 pk;
            if (isLo) {
                pk = __floats2bfloat162_rn(w0 - __bfloat162float(hb0),
                                           w1 - __bfloat162float(hb1));
            } else {
                pk.x = hb0; pk.y = hb1;
            }
            val = *reinterpret_cast<u32*>(&pk);
        }
        int phys = (g + (lane >> 1)) & 3;
        g_Wperm[(((r * 16 + w) * 32 + lane) << 4) + phys * 4 + part] = val;
    }
    for (int idx = i0; idx < 512; idx += st) {
        g_b0[idx] = bih0[idx] + bhh0[idx];
        g_b1[idx] = bih1[idx] + bhh1[idx];
    }
    for (int idx = i0; idx < H * FCH; idx += st) {
        int k = idx / FCH, j = idx % FCH;
        g_W1T[idx] = W1[j * H + k];
    }
    for (int idx = i0; idx < H; idx += st) {
        float s = gam[idx] * rsqrtf(var[idx] + 1e-5f);
        g_bnsc[idx] = s;
        g_bnsh[idx] = bet[idx] - mean[idx] * s;
    }
}

__device__ __forceinline__ float sigm(float v)  { return __fdividef(1.f, 1.f + __expf(-v)); }
__device__ __forceinline__ float tanhh(float v) { return 2.f * __fdividef(1.f, 1.f + __expf(-2.f * v)) - 1.f; }

__device__ __forceinline__ unsigned smem_u32(const void* p) {
    return (unsigned)__cvta_generic_to_shared(p);
}

__device__ __forceinline__ void pack_hilo(float a, float b, u32* ph, u32* pl) {
    __nv_bfloat16 ha = __float2bfloat16_rn(a), hb = __float2bfloat16_rn(b);
    __nv_bfloat162 hh; hh.x = ha; hh.y = hb;
    *ph = *reinterpret_cast<u32*>(&hh);
    __nv_bfloat162 ll = __floats2bfloat162_rn(a - __bfloat162float(ha),
                                              b - __bfloat162float(hb));
    *pl = *reinterpret_cast<u32*>(&ll);
}

// ---- mbarrier / bulk helpers ----
__device__ __forceinline__ void mbar_init(u32 a, u32 cnt) {
    asm volatile("mbarrier.init.shared.b64 [%0], %1;" :: "r"(a), "r"(cnt) : "memory");
}
__device__ __forceinline__ void mbar_expect(u32 a, u32 bytes) {
    asm volatile("mbarrier.arrive.expect_tx.shared.b64 _, [%0], %1;" :: "r"(a), "r"(bytes) : "memory");
}
// cluster-scope acquire: the cross-warp/CTA state handoff rides this chain
__device__ __forceinline__ void mbar_wait(u32 a, u32 parity) {
    asm volatile(
        "{\n\t.reg .pred P;\n\t"
        "WL%=:\n\t"
        "mbarrier.try_wait.parity.acquire.cluster.shared::cta.b64 P, [%0], %1, 0x989680;\n\t"
        "@P bra WD%=;\n\t"
        "bra WL%=;\n\t"
        "WD%=:\n\t}"
        :: "r"(a), "r"(parity) : "memory");
}
__device__ __forceinline__ void mbar_arrive_rank0(u32 a) {
    asm volatile(
        "{\n\t.reg .b32 ra;\n\t"
        "mapa.shared::cluster.u32 ra, %0, 0;\n\t"
        "mbarrier.arrive.release.cluster.shared::cluster.b64 _, [ra];\n\t}"
        :: "r"(a) : "memory");
}
__device__ __forceinline__ void bulk_mcast(u32 dst, const u32* src, u32 mbar) {
    asm volatile(
        "cp.async.bulk.shared::cluster.global.mbarrier::complete_tx::bytes.multicast::cluster "
        "[%0], [%1], %2, [%3], %4;"
        :: "r"(dst), "l"(src), "r"(32768u), "r"(mbar), "h"((unsigned short)0x3) : "memory");
}
#define CLUSTER_SYNC_() do { \
    asm volatile("barrier.cluster.arrive.aligned;" ::: "memory"); \
    asm volatile("barrier.cluster.wait.aligned;" ::: "memory"); \
} while (0)

__device__ __forceinline__ void mma16(float* d, u32 a0, u32 a1, u32 a2, u32 a3, u32 b0, u32 b1) {
    asm volatile("mma.sync.aligned.m16n8k16.row.col.f32.bf16.bf16.f32 "
                 "{%0,%1,%2,%3},{%4,%5,%6,%7},{%8,%9},{%0,%1,%2,%3};"
                 : "+f"(d[0]), "+f"(d[1]), "+f"(d[2]), "+f"(d[3])
                 : "r"(a0), "r"(a1), "r"(a2), "r"(a3), "r"(b0), "r"(b1));
}
__device__ __forceinline__ void mma8b(float* d, u32 a0, u32 a1, u32 b0) {
    asm volatile("mma.sync.aligned.m16n8k8.row.col.f32.bf16.bf16.f32 "
                 "{%0,%1,%2,%3},{%4,%5},{%6},{%0,%1,%2,%3};"
                 : "+f"(d[0]), "+f"(d[1]), "+f"(d[2]), "+f"(d[3])
                 : "r"(a0), "r"(a1), "r"(b0));
}

// one k16 chunk: 2 m-halves x 4 gates x 3 compensation terms = 24 MMAs
__device__ __forceinline__ void chunk16(float (&acc)[2][4][4], const uint4* __restrict__ bb4, int rot,
                                        const u32* __restrict__ aH, const u32* __restrict__ aL,
                                        int laneK, int laneM) {
    uint4 B[4];
#pragma unroll
    for (int g = 0; g < 4; g++) B[g] = bb4[(g + rot) & 3];
#pragma unroll
    for (int h = 0; h < 2; h++) {
        const u32* pH = aH + laneK * APW + h * 16 + laneM;
        const u32* pL = aL + laneK * APW + h * 16 + laneM;
        u32 a0 = pH[0], a1 = pH[8], a2 = pH[4 * APW], a3 = pH[4 * APW + 8];
        u32 l0 = pL[0], l1 = pL[8], l2 = pL[4 * APW], l3 = pL[4 * APW + 8];
#pragma unroll
        for (int g = 0; g < 4; g++) {
            mma16(acc[h][g], a0, a1, a2, a3, B[g].x, B[g].y);
            mma16(acc[h][g], l0, l1, l2, l3, B[g].x, B[g].y);
            mma16(acc[h][g], a0, a1, a2, a3, B[g].z, B[g].w);
        }
    }
}

// x chunk (k=8)
__device__ __forceinline__ void chunk8(float (&acc)[2][4][4], const uint4* __restrict__ bb4, int rot,
                                       const u32* __restrict__ aH, const u32* __restrict__ aL,
                                       int laneK, int laneM) {
    uint4 B[4];
#pragma unroll
    for (int g = 0; g < 4; g++) B[g] = bb4[(g + rot) & 3];
#pragma unroll
    for (int h = 0; h < 2; h++) {
        const u32* pH = aH + laneK * APW + h * 16 + laneM;
        const u32* pL = aL + laneK * APW + h * 16 + laneM;
        u32 a0 = pH[0], a1 = pH[8];
        u32 l0 = pL[0], l1 = pL[8];
#pragma unroll
        for (int g = 0; g < 4; g++) {
            mma8b(acc[h][g], a0, a1, B[g].x);
            mma8b(acc[h][g], l0, l1, B[g].x);
            mma8b(acc[h][g], a0, a1, B[g].z);
        }
    }
}

__device__ __forceinline__ void acc_init(float (&acc)[2][4][4], const float* __restrict__ shB,
                                         int wid, int laneK) {
    int j = wid * 8 + 2 * laneK;
#pragma unroll
    for (int g = 0; g < 4; g++) {
        float bj  = shB[g * 128 + j];
        float bj1 = shB[g * 128 + j + 1];
#pragma unroll
        for (int h = 0; h < 2; h++) {
            acc[h][g][0] = bj; acc[h][g][1] = bj1;
            acc[h][g][2] = bj; acc[h][g][3] = bj1;
        }
    }
}

__device__ __forceinline__ void epilogue(float (&acc)[2][4][4], float* cst,
                                         u32* __restrict__ hHb, u32* __restrict__ hLb,
                                         int wid, int laneK, int laneM) {
    int jp = wid * 4 + laneK;
#pragma unroll
    for (int h = 0; h < 2; h++) {
#pragma unroll
        for (int rr = 0; rr < 2; rr++) {
            int m = h * 16 + laneM + rr * 8;
            float hv[2];
#pragma unroll
            for (int q = 0; q < 2; q++) {
                float zi = acc[h][0][rr * 2 + q], zf = acc[h][1][rr * 2 + q];
                float zg = acc[h][2][rr * 2 + q], zo = acc[h][3][rr * 2 + q];
                int ci = h * 4 + rr * 2 + q;
                float c = sigm(zf) * cst[ci] + sigm(zi) * tanhh(zg);
                cst[ci] = c;
                hv[q] = sigm(zo) * tanhh(c);
            }
            pack_hilo(hv[0], hv[1], &hHb[jp * APW + m], &hLb[jp * APW + m]);
        }
    }
}

// smem layout (u32 units); h0 double-buffered
#define SM_XH   (NSLOT * CHUNKU)            // 32768
#define SM_XL   (SM_XH   + 4 * APW)
#define SM_H0HA (SM_XL   + 4 * APW)
#define SM_H0LA (SM_H0HA + 64 * APW)
#define SM_H0HB (SM_H0LA + 64 * APW)
#define SM_H0LB (SM_H0HB + 64 * APW)
#define SM_H1H  (SM_H0LB + 64 * APW)
#define SM_H1L  (SM_H1H  + 64 * APW)
#define SM_FLT  (SM_H1L  + 64 * APW)
#define NFLT    (512 + 512 + 128 + 128 + MB * FCH + MB * OUTD)
#define SM_MB   (SM_FLT + NFLT)             // 8 mbarriers (2 u32 each)
#define SM_TOTB ((SM_MB + 16) * 4)

__global__ void __launch_bounds__(NTHR, 1) __cluster_dims__(2, 1, 1)
lstm_main(const float* __restrict__ x,
          const float* __restrict__ W2, const float* __restrict__ b2,
          const float* __restrict__ Wf, const float* __restrict__ bf,
          const float* __restrict__ b1fc,
          float* __restrict__ out, int steps)
{
    extern __shared__ u32 smu[];
    u32* ring = smu;
    u32* xH  = smu + SM_XH;
    u32* xL  = smu + SM_XL;
    u32* h1H = smu + SM_H1H;
    u32* h1L = smu + SM_H1L;
    float* shB0  = (float*)(smu + SM_FLT);
    float* shB1  = shB0 + 512;
    float* shBNs = shB1 + 512;
    float* shBNh = shBNs + 128;
    float* shO1  = shBNh + 128;
    float* shO2  = shO1 + MB * FCH;

    const int tid  = threadIdx.x;
    const int wid  = tid >> 5, lane = tid & 31;
    const int laneK = lane & 3, laneM = lane >> 2;
    const int rot  = (lane >> 1) & 3;
    const int b0 = blockIdx.x * MB;
    u32 rank; asm("mov.u32 %0, %%cluster_ctarank;" : "=r"(rank));

    const u32 ringb = smem_u32(ring);
    const u32 mbF   = smem_u32(smu + SM_MB);          // full[0..3]
    const u32 mbE   = mbF + 32;                       // empty[0..3]

    if (tid == 0) {
#pragma unroll
        for (int s = 0; s < 4; s++) {
            mbar_init(mbF + s * 8, 1);
            mbar_init(mbE + s * 8, 32);
        }
    }
    // zero x + h0(A,B) + h1 buffers
    for (int i = tid; i < 8 * APW + 6 * 64 * APW; i += NTHR) xH[i] = 0;
    for (int i = tid; i < 512; i += NTHR) { shB0[i] = g_b0[i]; shB1[i] = g_b1[i]; }
    if (tid < H) { shBNs[tid] = g_bnsc[tid]; shBNh[tid] = g_bnsh[tid]; }

    float cst0[8], cst1[8];
#pragma unroll
    for (int i = 0; i < 8; i++) { cst0[i] = 0.f; cst1[i] = 0.f; }

    if (tid < 128) {
        int kp = tid >> 5, m = tid & 31;
        const float* xp = x + ((size_t)(b0 + m) * TT + 0) * IN_D + 2 * kp;
        pack_hilo(xp[0], xp[1], &xH[kp * APW + m], &xL[kp * APW + m]);
    }
    __syncthreads();                 // init published

    if (wid < 3 && lane == 0) mbar_expect(mbF + wid * 8, 32768u);
    CLUSTER_SYNC_();                 // inits + expects visible cluster-wide
    if (rank == 0 && wid < 3 && lane == 0)
        bulk_mcast(ringb + (u32)wid * 32768u, g_Wperm + (size_t)wid * CHUNKU, mbF + wid * 8);

    const int total = TT + steps;
    const int tiles_total = total * NCHUNK;
    int cglob = 0, prp = 3;

    u32* h0Hr = smu + SM_H0HA; u32* h0Lr = smu + SM_H0LA;
    u32* h0Hw = smu + SM_H0HB; u32* h0Lw = smu + SM_H0LB;

#define PIPE_BEGIN() do { \
    int pc = cglob + 3; \
    if (pc < tiles_total && wid == (pc & 3) && lane == 0) { \
        mbar_expect(mbF + (pc & 3) * 8, 32768u); \
        if (rank == 0) { \
            if (pc >= 4) mbar_wait(mbE + (pc & 3) * 8, ((pc >> 2) - 1) & 1); \
            bulk_mcast(ringb + (u32)(pc & 3) * 32768u, g_Wperm + (size_t)prp * CHUNKU, \
                       mbF + (pc & 3) * 8); \
        } \
    } \
    mbar_wait(mbF + (cglob & 3) * 8, (cglob >> 2) & 1); \
} while (0)

#define PIPE_END() do { \
    if (lane == 0) mbar_arrive_rank0(mbE + (cglob & 3) * 8); \
    cglob++; prp = (prp == NCHUNK - 1) ? 0 : prp + 1; \
} while (0)

    for (int t = 0; t < total; t++) {
        bool dec = (t >= TT);
        float acc[2][4][4];

        // ---- layer 0: x chunk + 8 h0(read) chunks ----
        acc_init(acc, shB0, wid, laneK);
        PIPE_BEGIN();
        chunk8(acc, (const uint4*)(ring + (cglob & 3) * CHUNKU + wid * 512 + lane * 16), rot,
               xH, xL, laneK, laneM);
        PIPE_END();
#pragma unroll
        for (int r = 0; r < 8; r++) {
            PIPE_BEGIN();
            chunk16(acc, (const uint4*)(ring + (cglob & 3) * CHUNKU + wid * 512 + lane * 16), rot,
                    h0Hr + r * 8 * APW, h0Lr + r * 8 * APW, laneK, laneM);
            PIPE_END();
        }
        // epi0 -> h0(write buffer); overlaps the following Whh1 chunks.
        // Safety: readers of h0w finished >= 2 ring-rounds ago; consumers of h0w
        // (chunks 17-24) are >= 9 chunks ahead -> ordered via the mbar ring chain.
        epilogue(acc, cst0, h0Hw, h0Lw, wid, laneK, laneM);
        if (!dec && t + 1 < TT && tid < 128) {
            int kp = tid >> 5, m = tid & 31;
            const float* xp = x + ((size_t)(b0 + m) * TT + (t + 1)) * IN_D + 2 * kp;
            pack_hilo(xp[0], xp[1], &xH[kp * APW + m], &xL[kp * APW + m]);
        }

        // ---- layer 1: 8 h1 (Whh1) chunks, then 8 h0(new) (Wih1) chunks ----
        acc_init(acc, shB1, wid, laneK);
#pragma unroll
        for (int r = 0; r < 8; r++) {
            PIPE_BEGIN();
            chunk16(acc, (const uint4*)(ring + (cglob & 3) * CHUNKU + wid * 512 + lane * 16), rot,
                    h1H + r * 8 * APW, h1L + r * 8 * APW, laneK, laneM);
            PIPE_END();
        }
#pragma unroll
        for (int r = 0; r < 8; r++) {
            PIPE_BEGIN();
            chunk16(acc, (const uint4*)(ring + (cglob & 3) * CHUNKU + wid * 512 + lane * 16), rot,
                    h0Hw + r * 8 * APW, h0Lw + r * 8 * APW, laneK, laneM);
            PIPE_END();
        }
        // epi1 in place: h1 readers (chunks 9-16) are >= 4 chunks behind by ring distance
        epilogue(acc, cst1, h1H, h1L, wid, laneK, laneM);

        if (dec) {
            int d = t - TT;
            __syncthreads();             // h1(new) visible to all
#pragma unroll
            for (int i = 0; i < (MB * FCH) / NTHR; i++) {
                int idx = tid + i * NTHR;
                int m = idx >> 6, n = idx & 63;
                float s = b1fc[n];
#pragma unroll 4
                for (int kp = 0; kp < 64; kp++) {
                    u32 wh = h1H[kp * APW + m], wl = h1L[kp * APW + m];
                    __nv_bfloat162 bh = *reinterpret_cast<__nv_bfloat162*>(&wh);
                    __nv_bfloat162 bl = *reinterpret_cast<__nv_bfloat162*>(&wl);
                    float ha = __bfloat162float(bh.x) + __bfloat162float(bl.x);
                    float hb = __bfloat162float(bh.y) + __bfloat162float(bl.y);
                    int k0 = 2 * kp;
                    float hn0 = ha * shBNs[k0] + shBNh[k0];
                    float hn1 = hb * shBNs[k0 + 1] + shBNh[k0 + 1];
                    s += hn0 * g_W1T[k0 * FCH + n] + hn1 * g_W1T[(k0 + 1) * FCH + n];
                }
                shO1[idx] = fmaxf(s, 0.f);
            }
            __syncthreads();
            if (tid < MB * OUTD) {
                int m = tid >> 2, o = tid & 3;
                float s = b2[o];
#pragma unroll 8
                for (int k = 0; k < FCH; k++) s += shO1[m * FCH + k] * W2[o * FCH + k];
                shO2[tid] = s;
                out[((size_t)(b0 + m) * steps + d) * OUTD + o] = s;
            }
            __syncthreads();
            if (tid < 128) {
                int kp = tid >> 5, m = tid & 31;
                float s0 = bf[2 * kp], s1 = bf[2 * kp + 1];
#pragma unroll
                for (int o = 0; o < OUTD; o++) {
                    float ov = shO2[m * OUTD + o];
                    s0 += ov * Wf[(2 * kp) * OUTD + o];
                    s1 += ov * Wf[(2 * kp + 1) * OUTD + o];
                }
                pack_hilo(s0, s1, &xH[kp * APW + m], &xL[kp * APW + m]);
            }
            __syncthreads();             // x(next) published before next L0
        }

        // swap h0 buffers
        u32* tp;
        tp = h0Hr; h0Hr = h0Hw; h0Hw = tp;
        tp = h0Lr; h0Lr = h0Lw; h0Lw = tp;
    }
#undef PIPE_BEGIN
#undef PIPE_END
    CLUSTER_SYNC_();                     // no CTA exits with peer traffic in flight
}

extern "C" void kernel_launch(void* const* d_in, const int* in_sizes, int n_in,
                              void* d_out, int out_size) {
    const float* x    = (const float*)d_in[0];
    const float* Wih0 = (const float*)d_in[1];
    const float* Whh0 = (const float*)d_in[2];
    const float* bih0 = (const float*)d_in[3];
    const float* bhh0 = (const float*)d_in[4];
    const float* Wih1 = (const float*)d_in[5];
    const float* Whh1 = (const float*)d_in[6];
    const float* bih1 = (const float*)d_in[7];
    const float* bhh1 = (const float*)d_in[8];
    const float* gam  = (const float*)d_in[9];
    const float* bet  = (const float*)d_in[10];
    const float* mean = (const float*)d_in[11];
    const float* var  = (const float*)d_in[12];
    const float* W1   = (const float*)d_in[13];
    const float* b1   = (const float*)d_in[14];
    const float* W2   = (const float*)d_in[15];
    const float* b2   = (const float*)d_in[16];
    const float* Wf   = (const float*)d_in[17];
    const float* bf   = (const float*)d_in[18];
    float* out = (float*)d_out;

    int B = in_sizes[0] / (TT * IN_D);
    int steps = out_size / (B * OUTD);

    cudaFuncSetAttribute(lstm_main, cudaFuncAttributeMaxDynamicSharedMemorySize, SM_TOTB);

    prep_kernel<<<256, 256>>>(Wih0, Whh0, bih0, bhh0, Wih1, Whh1, bih1, bhh1,
                              gam, bet, mean, var, W1);
    lstm_main<<<B / MB, NTHR, SM_TOTB>>>(x, W2, b2, Wf, bf, b1, out, steps);
}

// round 15
// speedup vs baseline: 1.5948x; 1.5948x over previous
#include <cuda_runtime.h>
#include <cuda_bf16.h>

#define H      128
#define IN_D   8
#define TT     512
#define OUTD   4
#define FCH    64
#define MB     32
#define NTHR   512
#define NCHUNK 25               // chunks per step: 1(Wih0,k8) + 8(Whh0) + 8(Whh1) + 8(Wih1)
#define APW    40               // u32 row stride of activation buffers (32 + 8 pad)
#define CHUNKU 8192             // u32 per chunk (32 KB): 16 warps x 32 lanes x 16
#define NSLOT  4

typedef unsigned u32;

// weights permuted to per-(chunk, warp, lane) fragment order, bf16 hi/lo packed,
// uint4-rotated within each lane block for conflict-free LDS.128 without padding
__device__ __align__(128) u32 g_Wperm[NCHUNK * CHUNKU];   // 800KB
__device__ float g_W1T[H * FCH];
__device__ float g_b0[512], g_b1[512], g_bnsc[H], g_bnsh[H];

__global__ void prep_kernel(const float* __restrict__ Wih0, const float* __restrict__ Whh0,
                            const float* __restrict__ bih0, const float* __restrict__ bhh0,
                            const float* __restrict__ Wih1, const float* __restrict__ Whh1,
                            const float* __restrict__ bih1, const float* __restrict__ bhh1,
                            const float* __restrict__ gam,  const float* __restrict__ bet,
                            const float* __restrict__ mean, const float* __restrict__ var,
                            const float* __restrict__ W1)
{
    int i0 = blockIdx.x * blockDim.x + threadIdx.x;
    int st = gridDim.x * blockDim.x;

    for (int idx = i0; idx < NCHUNK * 16 * 32 * 16; idx += st) {
        int part = idx & 3;          // u32 within logical uint4
        int g    = (idx >> 2) & 3;   // logical uint4 index = gate
        int lane = (idx >> 4) & 31;
        int w    = (idx >> 9) & 15;
        int r    = idx >> 13;
        int laneK = lane & 3, laneM = lane >> 2;
        int n = g * 128 + w * 8 + laneM;            // output column 0..511
        int kk = 2 * laneK + ((part & 1) ? 8 : 0);  // k within chunk
        bool isLo = (part >= 2);
        const float* Wm; int K, kb;
        if (r == 0)       { Wm = Wih0; K = IN_D; kb = 0; }
        else if (r <= 8)  { Wm = Whh0; K = H; kb = (r - 1)  * 16; }
        else if (r <= 16) { Wm = Whh1; K = H; kb = (r - 9)  * 16; }   // h1 half first
        else              { Wm = Wih1; K = H; kb = (r - 17) * 16; }   // h0(new) half second
        u32 val = 0;
        if (kb + kk < K) {
            float w0 = Wm[n * K + kb + kk];
            float w1 = Wm[n * K + kb + kk + 1];
            __nv_bfloat16 hb0 = __float2bfloat16_rn(w0);
            __nv_bfloat16 hb1 = __float2bfloat16_rn(w1);
            __nv_bfloat162 pk;
            if (isLo) {
                pk = __floats2bfloat162_rn(w0 - __bfloat162float(hb0),
                                           w1 - __bfloat162float(hb1));
            } else {
                pk.x = hb0; pk.y = hb1;
            }
            val = *reinterpret_cast<u32*>(&pk);
        }
        int phys = (g + (lane >> 1)) & 3;
        g_Wperm[(((r * 16 + w) * 32 + lane) << 4) + phys * 4 + part] = val;
    }
    for (int idx = i0; idx < 512; idx += st) {
        g_b0[idx] = bih0[idx] + bhh0[idx];
        g_b1[idx] = bih1[idx] + bhh1[idx];
    }
    for (int idx = i0; idx < H * FCH; idx += st) {
        int k = idx / FCH, j = idx % FCH;
        g_W1T[idx] = W1[j * H + k];
    }
    for (int idx = i0; idx < H; idx += st) {
        float s = gam[idx] * rsqrtf(var[idx] + 1e-5f);
        g_bnsc[idx] = s;
        g_bnsh[idx] = bet[idx] - mean[idx] * s;
    }
}

__device__ __forceinline__ float sigm(float v)  { return __fdividef(1.f, 1.f + __expf(-v)); }
__device__ __forceinline__ float tanhh(float v) { return 2.f * __fdividef(1.f, 1.f + __expf(-2.f * v)) - 1.f; }

__device__ __forceinline__ unsigned smem_u32(const void* p) {
    return (unsigned)__cvta_generic_to_shared(p);
}

__device__ __forceinline__ void pack_hilo(float a, float b, u32* ph, u32* pl) {
    __nv_bfloat16 ha = __float2bfloat16_rn(a), hb = __float2bfloat16_rn(b);
    __nv_bfloat162 hh; hh.x = ha; hh.y = hb;
    *ph = *reinterpret_cast<u32*>(&hh);
    __nv_bfloat162 ll = __floats2bfloat162_rn(a - __bfloat162float(ha),
                                              b - __bfloat162float(hb));
    *pl = *reinterpret_cast<u32*>(&ll);
}

// ---- mbarrier / bulk helpers (R13 scopes: cheap cta-acquire waits) ----
__device__ __forceinline__ void mbar_init(u32 a, u32 cnt) {
    asm volatile("mbarrier.init.shared.b64 [%0], %1;" :: "r"(a), "r"(cnt) : "memory");
}
__device__ __forceinline__ void mbar_expect(u32 a, u32 bytes) {
    asm volatile("mbarrier.arrive.expect_tx.shared.b64 _, [%0], %1;" :: "r"(a), "r"(bytes) : "memory");
}
__device__ __forceinline__ void mbar_wait(u32 a, u32 parity) {
    asm volatile(
        "{\n\t.reg .pred P;\n\t"
        "WL%=:\n\t"
        "mbarrier.try_wait.parity.acquire.cta.shared::cta.b64 P, [%0], %1, 0x989680;\n\t"
        "@P bra WD%=;\n\t"
        "bra WL%=;\n\t"
        "WD%=:\n\t}"
        :: "r"(a), "r"(parity) : "memory");
}
__device__ __forceinline__ void mbar_arrive_rank0(u32 a) {
    asm volatile(
        "{\n\t.reg .b32 ra;\n\t"
        "mapa.shared::cluster.u32 ra, %0, 0;\n\t"
        "mbarrier.arrive.shared::cluster.b64 _, [ra];\n\t}"
        :: "r"(a) : "memory");
}
__device__ __forceinline__ void bulk_mcast(u32 dst, const u32* src, u32 mbar) {
    asm volatile(
        "cp.async.bulk.shared::cluster.global.mbarrier::complete_tx::bytes.multicast::cluster "
        "[%0], [%1], %2, [%3], %4;"
        :: "r"(dst), "l"(src), "r"(32768u), "r"(mbar), "h"((unsigned short)0x3) : "memory");
}
#define CLUSTER_SYNC_() do { \
    asm volatile("barrier.cluster.arrive.aligned;" ::: "memory"); \
    asm volatile("barrier.cluster.wait.aligned;" ::: "memory"); \
} while (0)

__device__ __forceinline__ void mma16(float* d, u32 a0, u32 a1, u32 a2, u32 a3, u32 b0, u32 b1) {
    asm volatile("mma.sync.aligned.m16n8k16.row.col.f32.bf16.bf16.f32 "
                 "{%0,%1,%2,%3},{%4,%5,%6,%7},{%8,%9},{%0,%1,%2,%3};"
                 : "+f"(d[0]), "+f"(d[1]), "+f"(d[2]), "+f"(d[3])
                 : "r"(a0), "r"(a1), "r"(a2), "r"(a3), "r"(b0), "r"(b1));
}
__device__ __forceinline__ void mma8b(float* d, u32 a0, u32 a1, u32 b0) {
    asm volatile("mma.sync.aligned.m16n8k8.row.col.f32.bf16.bf16.f32 "
                 "{%0,%1,%2,%3},{%4,%5},{%6},{%0,%1,%2,%3};"
                 : "+f"(d[0]), "+f"(d[1]), "+f"(d[2]), "+f"(d[3])
                 : "r"(a0), "r"(a1), "r"(b0));
}

// one k16 chunk: 2 m-halves x 4 gates x 3 compensation terms = 24 MMAs
__device__ __forceinline__ void chunk16(float (&acc)[2][4][4], const uint4* __restrict__ bb4, int rot,
                                        const u32* __restrict__ aH, const u32* __restrict__ aL,
                                        int laneK, int laneM) {
    uint4 B[4];
#pragma unroll
    for (int g = 0; g < 4; g++) B[g] = bb4[(g + rot) & 3];
#pragma unroll
    for (int h = 0; h < 2; h++) {
        const u32* pH = aH + laneK * APW + h * 16 + laneM;
        const u32* pL = aL + laneK * APW + h * 16 + laneM;
        u32 a0 = pH[0], a1 = pH[8], a2 = pH[4 * APW], a3 = pH[4 * APW + 8];
        u32 l0 = pL[0], l1 = pL[8], l2 = pL[4 * APW], l3 = pL[4 * APW + 8];
#pragma unroll
        for (int g = 0; g < 4; g++) {
            mma16(acc[h][g], a0, a1, a2, a3, B[g].x, B[g].y);
            mma16(acc[h][g], l0, l1, l2, l3, B[g].x, B[g].y);
            mma16(acc[h][g], a0, a1, a2, a3, B[g].z, B[g].w);
        }
    }
}

// x chunk (k=8)
__device__ __forceinline__ void chunk8(float (&acc)[2][4][4], const uint4* __restrict__ bb4, int rot,
                                       const u32* __restrict__ aH, const u32* __restrict__ aL,
                                       int laneK, int laneM) {
    uint4 B[4];
#pragma unroll
    for (int g = 0; g < 4; g++) B[g] = bb4[(g + rot) & 3];
#pragma unroll
    for (int h = 0; h < 2; h++) {
        const u32* pH = aH + laneK * APW + h * 16 + laneM;
        const u32* pL = aL + laneK * APW + h * 16 + laneM;
        u32 a0 = pH[0], a1 = pH[8];
        u32 l0 = pL[0], l1 = pL[8];
#pragma unroll
        for (int g = 0; g < 4; g++) {
            mma8b(acc[h][g], a0, a1, B[g].x);
            mma8b(acc[h][g], l0, l1, B[g].x);
            mma8b(acc[h][g], a0, a1, B[g].z);
        }
    }
}

__device__ __forceinline__ void acc_init(float (&acc)[2][4][4], const float* __restrict__ shB,
                                         int wid, int laneK) {
    int j = wid * 8 + 2 * laneK;
#pragma unroll
    for (int g = 0; g < 4; g++) {
        float bj  = shB[g * 128 + j];
        float bj1 = shB[g * 128 + j + 1];
#pragma unroll
        for (int h = 0; h < 2; h++) {
            acc[h][g][0] = bj; acc[h][g][1] = bj1;
            acc[h][g][2] = bj; acc[h][g][3] = bj1;
        }
    }
}

__device__ __forceinline__ void epilogue(float (&acc)[2][4][4], float* cst,
                                         u32* __restrict__ hHb, u32* __restrict__ hLb,
                                         int wid, int laneK, int laneM) {
    int jp = wid * 4 + laneK;
#pragma unroll
    for (int h = 0; h < 2; h++) {
#pragma unroll
        for (int rr = 0; rr < 2; rr++) {
            int m = h * 16 + laneM + rr * 8;
            float hv[2];
#pragma unroll
            for (int q = 0; q < 2; q++) {
                float zi = acc[h][0][rr * 2 + q], zf = acc[h][1][rr * 2 + q];
                float zg = acc[h][2][rr * 2 + q], zo = acc[h][3][rr * 2 + q];
                int ci = h * 4 + rr * 2 + q;
                float c = sigm(zf) * cst[ci] + sigm(zi) * tanhh(zg);
                cst[ci] = c;
                hv[q] = sigm(zo) * tanhh(c);
            }
            pack_hilo(hv[0], hv[1], &hHb[jp * APW + m], &hLb[jp * APW + m]);
        }
    }
}

// smem layout (u32 units); h0 double-buffered
#define SM_XH   (NSLOT * CHUNKU)            // 32768
#define SM_XL   (SM_XH   + 4 * APW)
#define SM_H0HA (SM_XL   + 4 * APW)
#define SM_H0LA (SM_H0HA + 64 * APW)
#define SM_H0HB (SM_H0LA + 64 * APW)
#define SM_H0LB (SM_H0HB + 64 * APW)
#define SM_H1H  (SM_H0LB + 64 * APW)
#define SM_H1L  (SM_H1H  + 64 * APW)
#define SM_FLT  (SM_H1L  + 64 * APW)
#define NFLT    (512 + 512 + 128 + 128 + MB * FCH + MB * OUTD)
#define SM_MB   (SM_FLT + NFLT)             // 8 mbarriers (2 u32 each)
#define SM_TOTB ((SM_MB + 16) * 4)

__global__ void __launch_bounds__(NTHR, 1) __cluster_dims__(2, 1, 1)
lstm_main(const float* __restrict__ x,
          const float* __restrict__ W2, const float* __restrict__ b2,
          const float* __restrict__ Wf, const float* __restrict__ bf,
          const float* __restrict__ b1fc,
          float* __restrict__ out, int steps)
{
    extern __shared__ u32 smu[];
    u32* ring = smu;
    u32* xH  = smu + SM_XH;
    u32* xL  = smu + SM_XL;
    u32* h1H = smu + SM_H1H;
    u32* h1L = smu + SM_H1L;
    float* shB0  = (float*)(smu + SM_FLT);
    float* shB1  = shB0 + 512;
    float* shBNs = shB1 + 512;
    float* shBNh = shBNs + 128;
    float* shO1  = shBNh + 128;
    float* shO2  = shO1 + MB * FCH;

    const int tid  = threadIdx.x;
    const int wid  = tid >> 5, lane = tid & 31;
    const int laneK = lane & 3, laneM = lane >> 2;
    const int rot  = (lane >> 1) & 3;
    const int b0 = blockIdx.x * MB;
    u32 rank; asm("mov.u32 %0, %%cluster_ctarank;" : "=r"(rank));

    const u32 ringb = smem_u32(ring);
    const u32 mbF   = smem_u32(smu + SM_MB);          // full[0..3]
    const u32 mbE   = mbF + 32;                       // empty[0..3]

    if (tid == 0) {
#pragma unroll
        for (int s = 0; s < 4; s++) {
            mbar_init(mbF + s * 8, 1);
            mbar_init(mbE + s * 8, 32);
        }
    }
    // zero x + h0(A,B) + h1 buffers
    for (int i = tid; i < 8 * APW + 6 * 64 * APW; i += NTHR) xH[i] = 0;
    for (int i = tid; i < 512; i += NTHR) { shB0[i] = g_b0[i]; shB1[i] = g_b1[i]; }
    if (tid < H) { shBNs[tid] = g_bnsc[tid]; shBNh[tid] = g_bnsh[tid]; }

    float cst0[8], cst1[8];
#pragma unroll
    for (int i = 0; i < 8; i++) { cst0[i] = 0.f; cst1[i] = 0.f; }

    if (tid < 128) {
        int kp = tid >> 5, m = tid & 31;
        const float* xp = x + ((size_t)(b0 + m) * TT + 0) * IN_D + 2 * kp;
        pack_hilo(xp[0], xp[1], &xH[kp * APW + m], &xL[kp * APW + m]);
    }
    __syncthreads();                 // init published

    if (wid < 3 && lane == 0) mbar_expect(mbF + wid * 8, 32768u);
    CLUSTER_SYNC_();                 // inits + expects visible cluster-wide
    if (rank == 0 && wid < 3 && lane == 0)
        bulk_mcast(ringb + (u32)wid * 32768u, g_Wperm + (size_t)wid * CHUNKU, mbF + wid * 8);

    const int total = TT + steps;
    const int tiles_total = total * NCHUNK;
    int cglob = 0, prp = 3;

    u32* h0Hr = smu + SM_H0HA; u32* h0Lr = smu + SM_H0LA;
    u32* h0Hw = smu + SM_H0HB; u32* h0Lw = smu + SM_H0LB;

#define PIPE_BEGIN() do { \
    int pc = cglob + 3; \
    if (pc < tiles_total && wid == (pc & 3) && lane == 0) { \
        mbar_expect(mbF + (pc & 3) * 8, 32768u); \
        if (rank == 0) { \
            if (pc >= 4) mbar_wait(mbE + (pc & 3) * 8, ((pc >> 2) - 1) & 1); \
            bulk_mcast(ringb + (u32)(pc & 3) * 32768u, g_Wperm + (size_t)prp * CHUNKU, \
                       mbF + (pc & 3) * 8); \
        } \
    } \
    mbar_wait(mbF + (cglob & 3) * 8, (cglob >> 2) & 1); \
} while (0)

#define PIPE_END() do { \
    if (lane == 0) mbar_arrive_rank0(mbE + (cglob & 3) * 8); \
    cglob++; prp = (prp == NCHUNK - 1) ? 0 : prp + 1; \
} while (0)

    for (int t = 0; t < total; t++) {
        bool dec = (t >= TT);
        float acc[2][4][4];

        // ---- layer 0: x chunk + 8 Whh0 chunks (read x, h0r) ----
        acc_init(acc, shB0, wid, laneK);
        PIPE_BEGIN();
        chunk8(acc, (const uint4*)(ring + (cglob & 3) * CHUNKU + wid * 512 + lane * 16), rot,
               xH, xL, laneK, laneM);
        PIPE_END();
#pragma unroll
        for (int r = 0; r < 8; r++) {
            PIPE_BEGIN();
            chunk16(acc, (const uint4*)(ring + (cglob & 3) * CHUNKU + wid * 512 + lane * 16), rot,
                    h0Hr + r * 8 * APW, h0Lr + r * 8 * APW, laneK, laneM);
            PIPE_END();
        }
        // epi0 -> h0 write buffer (no barrier needed: different buffer than h0r)
        epilogue(acc, cst0, h0Hw, h0Lw, wid, laneK, laneM);
        // stage next encoder x (this step's x readers are this warp's chunk0, done)
        if (!dec && t + 1 < TT && tid < 128) {
            int kp = tid >> 5, m = tid & 31;
            const float* xp = x + ((size_t)(b0 + m) * TT + (t + 1)) * IN_D + 2 * kp;
            pack_hilo(xp[0], xp[1], &xH[kp * APW + m], &xL[kp * APW + m]);
        }

        // ---- layer 1 phase A: 8 Whh1 chunks (read h1) — independent of epi0 ----
        acc_init(acc, shB1, wid, laneK);
#pragma unroll
        for (int r = 0; r < 8; r++) {
            PIPE_BEGIN();
            chunk16(acc, (const uint4*)(ring + (cglob & 3) * CHUNKU + wid * 512 + lane * 16), rot,
                    h1H + r * 8 * APW, h1L + r * 8 * APW, laneK, laneM);
            PIPE_END();
        }
        __syncthreads();     // publishes h0w; all h1 reads of this step complete

        // ---- layer 1 phase B: 8 Wih1 chunks (read h0w) ----
#pragma unroll
        for (int r = 0; r < 8; r++) {
            PIPE_BEGIN();
            chunk16(acc, (const uint4*)(ring + (cglob & 3) * CHUNKU + wid * 512 + lane * 16), rot,
                    h0Hw + r * 8 * APW, h0Lw + r * 8 * APW, laneK, laneM);
            PIPE_END();
        }
        // epi1 in place: all h1 readers passed the sync above
        epilogue(acc, cst1, h1H, h1L, wid, laneK, laneM);

        if (!dec) {
            __syncthreads(); // publishes h1(new) + x(next) for next step
        } else {
            int d = t - TT;
            __syncthreads();             // h1(new) visible to all
#pragma unroll
            for (int i = 0; i < (MB * FCH) / NTHR; i++) {
                int idx = tid + i * NTHR;
                int m = idx >> 6, n = idx & 63;
                float s = b1fc[n];
#pragma unroll 4
                for (int kp = 0; kp < 64; kp++) {
                    u32 wh = h1H[kp * APW + m], wl = h1L[kp * APW + m];
                    __nv_bfloat162 bh = *reinterpret_cast<__nv_bfloat162*>(&wh);
                    __nv_bfloat162 bl = *reinterpret_cast<__nv_bfloat162*>(&wl);
                    float ha = __bfloat162float(bh.x) + __bfloat162float(bl.x);
                    float hb = __bfloat162float(bh.y) + __bfloat162float(bl.y);
                    int k0 = 2 * kp;
                    float hn0 = ha * shBNs[k0] + shBNh[k0];
                    float hn1 = hb * shBNs[k0 + 1] + shBNh[k0 + 1];
                    s += hn0 * g_W1T[k0 * FCH + n] + hn1 * g_W1T[(k0 + 1) * FCH + n];
                }
                shO1[idx] = fmaxf(s, 0.f);
            }
            __syncthreads();
            if (tid < MB * OUTD) {
                int m = tid >> 2, o = tid & 3;
                float s = b2[o];
#pragma unroll 8
                for (int k = 0; k < FCH; k++) s += shO1[m * FCH + k] * W2[o * FCH + k];
                shO2[tid] = s;
                out[((size_t)(b0 + m) * steps + d) * OUTD + o] = s;
            }
            __syncthreads();
            if (tid < 128) {
                int kp = tid >> 5, m = tid & 31;
                float s0 = bf[2 * kp], s1 = bf[2 * kp + 1];
#pragma unroll
                for (int o = 0; o < OUTD; o++) {
                    float ov = shO2[m * OUTD + o];
                    s0 += ov * Wf[(2 * kp) * OUTD + o];
                    s1 += ov * Wf[(2 * kp + 1) * OUTD + o];
                }
                pack_hilo(s0, s1, &xH[kp * APW + m], &xL[kp * APW + m]);
            }
            __syncthreads();             // x(next) published before next L0
        }

        // swap h0 buffers
        u32* tp;
        tp = h0Hr; h0Hr = h0Hw; h0Hw = tp;
        tp = h0Lr; h0Lr = h0Lw; h0Lw = tp;
    }
#undef PIPE_BEGIN
#undef PIPE_END
    CLUSTER_SYNC_();                     // no CTA exits with peer traffic in flight
}

extern "C" void kernel_launch(void* const* d_in, const int* in_sizes, int n_in,
                              void* d_out, int out_size) {
    const float* x    = (const float*)d_in[0];
    const float* Wih0 = (const float*)d_in[1];
    const float* Whh0 = (const float*)d_in[2];
    const float* bih0 = (const float*)d_in[3];
    const float* bhh0 = (const float*)d_in[4];
    const float* Wih1 = (const float*)d_in[5];
    const float* Whh1 = (const float*)d_in[6];
    const float* bih1 = (const float*)d_in[7];
    const float* bhh1 = (const float*)d_in[8];
    const float* gam  = (const float*)d_in[9];
    const float* bet  = (const float*)d_in[10];
    const float* mean = (const float*)d_in[11];
    const float* var  = (const float*)d_in[12];
    const float* W1   = (const float*)d_in[13];
    const float* b1   = (const float*)d_in[14];
    const float* W2   = (const float*)d_in[15];
    const float* b2   = (const float*)d_in[16];
    const float* Wf   = (const float*)d_in[17];
    const float* bf   = (const float*)d_in[18];
    float* out = (float*)d_out;

    int B = in_sizes[0] / (TT * IN_D);
    int steps = out_size / (B * OUTD);

    cudaFuncSetAttribute(lstm_main, cudaFuncAttributeMaxDynamicSharedMemorySize, SM_TOTB);

    prep_kernel<<<256, 256>>>(Wih0, Whh0, bih0, bhh0, Wih1, Whh1, bih1, bhh1,
                              gam, bet, mean, var, W1);
    lstm_main<<<B / MB, NTHR, SM_TOTB>>>(x, W2, b2, Wf, bf, b1, out, steps);
}